// round 4
// baseline (speedup 1.0000x reference)
#include <cuda_runtime.h>
#include <math.h>

#define N_NODES 100000
#define E_EDGES 1600000
// HID = 64, IN = 128, HEADS = 2

// ---------------- scratch (device globals; no allocations allowed) ----------
__device__ float g_dinv[N_NODES];              // deg -> dinv (in place)
__device__ float g_h[N_NODES * 64];            // x @ gcn_w
__device__ float g_acc[N_NODES * 64];          // GCN accumulator -> hg after relu (in place)
__device__ float g_h2[N_NODES * 128];          // hg @ gat_w  [N, 2 heads, 64]
__device__ float g_ss[N_NODES * 2];            // score_src per (node, head)
__device__ float g_sd[N_NODES * 2];            // score_dst per (node, head)
__device__ float g_denom[N_NODES * 2];         // softmax denominator (no max shift)
__device__ float g_out_acc[N_NODES * 64];      // GAT accumulator (head-mean folded)

// ---------------- helpers ----------------------------------------------------
__device__ __forceinline__ void red_add_v4(float* addr, float4 v) {
    asm volatile("red.global.add.v4.f32 [%0], {%1, %2, %3, %4};"
                 :: "l"(addr), "f"(v.x), "f"(v.y), "f"(v.z), "f"(v.w)
                 : "memory");
}
__device__ __forceinline__ float leaky(float a) {
    return a >= 0.f ? a : 0.2f * a;
}
__device__ __forceinline__ float elem4(float4 v, int kk) {
    return (kk == 0) ? v.x : (kk == 1) ? v.y : (kk == 2) ? v.z : v.w;
}

// ---------------- degree / norm ----------------------------------------------
__global__ void k_deg_init() {
    int t = blockIdx.x * blockDim.x + threadIdx.x;
    if (t < N_NODES) g_dinv[t] = 1.0f;   // self-loop weight 1
}
__global__ void k_deg_edges(const int* __restrict__ dst, const float* __restrict__ ew) {
    int e = blockIdx.x * blockDim.x + threadIdx.x;
    if (e < E_EDGES) atomicAdd(&g_dinv[dst[e]], ew[e]);
}
__global__ void k_dinv() {
    int t = blockIdx.x * blockDim.x + threadIdx.x;
    if (t < N_NODES) g_dinv[t] = rsqrtf(g_dinv[t]);   // deg >= 1 always
}

// ---------------- GEMM1: g_h = x[N,128] @ gcn_w[128,64]  (+ gcn self fold) ---
// 8 nodes x 8 cols per thread: 0.5B LDS + 0.5B LDG per FFMA.
// Block 256 thr = 8 col-groups x 32 node-groups(8 nodes) -> 256 nodes/block.
// Epilogue also writes g_acc = dinv^2 * h  (GCN self-loop term).
__global__ void __launch_bounds__(256, 2)
k_gemm1(const float* __restrict__ x, const float* __restrict__ W) {
    __shared__ float Ws[128 * 64];
    int tid = threadIdx.x;
    for (int i = tid * 4; i < 128 * 64; i += 256 * 4)
        *(float4*)&Ws[i] = *(const float4*)&W[i];
    __syncthreads();

    int cg = tid & 7;          // cols cg*8 .. cg*8+7
    int ng = tid >> 3;         // node group (0..31)
    int n0 = blockIdx.x * 256 + ng * 8;
    int c0 = cg * 8;

    const float4* xr[8];
#pragma unroll
    for (int i = 0; i < 8; i++) {
        int n = n0 + i; if (n >= N_NODES) n = N_NODES - 1;
        xr[i] = (const float4*)(x + (size_t)n * 128);
    }

    float acc[8][8];
#pragma unroll
    for (int i = 0; i < 8; i++)
#pragma unroll
        for (int j = 0; j < 8; j++) acc[i][j] = 0.f;

#pragma unroll 1
    for (int k4 = 0; k4 < 32; k4++) {
        float4 xv[8];
#pragma unroll
        for (int i = 0; i < 8; i++) xv[i] = __ldg(&xr[i][k4]);
#pragma unroll
        for (int kk = 0; kk < 4; kk++) {
            const float* wrow = &Ws[(k4 * 4 + kk) * 64 + c0];
            float4 w0 = *(const float4*)&wrow[0];
            float4 w1 = *(const float4*)&wrow[4];
#pragma unroll
            for (int i = 0; i < 8; i++) {
                float xs = elem4(xv[i], kk);
                acc[i][0] += xs * w0.x; acc[i][1] += xs * w0.y;
                acc[i][2] += xs * w0.z; acc[i][3] += xs * w0.w;
                acc[i][4] += xs * w1.x; acc[i][5] += xs * w1.y;
                acc[i][6] += xs * w1.z; acc[i][7] += xs * w1.w;
            }
        }
    }
#pragma unroll
    for (int i = 0; i < 8; i++) {
        int n = n0 + i;
        if (n >= N_NODES) break;
        float di = g_dinv[n];
        float c = di * di;
        float* hout = &g_h[(size_t)n * 64 + c0];
        float* aout = &g_acc[(size_t)n * 64 + c0];
        *(float4*)&hout[0] = make_float4(acc[i][0], acc[i][1], acc[i][2], acc[i][3]);
        *(float4*)&hout[4] = make_float4(acc[i][4], acc[i][5], acc[i][6], acc[i][7]);
        *(float4*)&aout[0] = make_float4(c * acc[i][0], c * acc[i][1], c * acc[i][2], c * acc[i][3]);
        *(float4*)&aout[4] = make_float4(c * acc[i][4], c * acc[i][5], c * acc[i][6], c * acc[i][7]);
    }
}

// ---------------- GCN edge aggregation ---------------------------------------
__global__ void k_gcn_edges(const int* __restrict__ src, const int* __restrict__ dst,
                            const float* __restrict__ ew) {
    int g = blockIdx.x * blockDim.x + threadIdx.x;
    int e = g >> 4;
    if (e >= E_EDGES) return;
    int t = threadIdx.x & 15;
    int s = __ldg(&src[e]);
    int d = __ldg(&dst[e]);
    float norm = 0.f;
    if (t == 0) norm = g_dinv[s] * __ldg(&ew[e]) * g_dinv[d];
    norm = __shfl_sync(0xffffffffu, norm, 0, 16);
    float4 h = *(const float4*)&g_h[(size_t)s * 64 + t * 4];
    red_add_v4(&g_acc[(size_t)d * 64 + t * 4],
               make_float4(norm * h.x, norm * h.y, norm * h.z, norm * h.w));
}

__global__ void k_gcn_final(const float* __restrict__ b) {
    int t = blockIdx.x * blockDim.x + threadIdx.x;
    if (t >= N_NODES * 16) return;
    int q = t & 15;
    float4 a = *(const float4*)&g_acc[(size_t)t * 4];
    float4 bv = *(const float4*)&b[q * 4];
    a.x = fmaxf(a.x + bv.x, 0.f);
    a.y = fmaxf(a.y + bv.y, 0.f);
    a.z = fmaxf(a.z + bv.z, 0.f);
    a.w = fmaxf(a.w + bv.w, 0.f);
    *(float4*)&g_acc[(size_t)t * 4] = a;    // g_acc is now hg
}

// ---------------- GEMM2: g_h2 = hg[N,64] @ gat_w[64,128] ---------------------
// 8 nodes x 8 cols per thread. Block 256 thr = 16 cg x 16 ng -> 128 nodes/blk.
// Epilogue: per-node attention scores (shfl-reduced over the 8-lane col group)
// + softmax denominator init with the self-loop term (no max shift).
__global__ void __launch_bounds__(256, 2)
k_gemm2(const float* __restrict__ W, const float* __restrict__ as_,
        const float* __restrict__ ad_) {
    __shared__ float Ws[64 * 128];
    int tid = threadIdx.x;
    for (int i = tid * 4; i < 64 * 128; i += 256 * 4)
        *(float4*)&Ws[i] = *(const float4*)&W[i];
    __syncthreads();

    int cg = tid & 15;         // cols cg*8 .. cg*8+7  (cg<8: head0, cg>=8: head1)
    int ng = tid >> 4;         // node group (0..15)
    int n0 = blockIdx.x * 128 + ng * 8;
    int c0 = cg * 8;

    const float4* xr[8];
#pragma unroll
    for (int i = 0; i < 8; i++) {
        int n = n0 + i; if (n >= N_NODES) n = N_NODES - 1;
        xr[i] = (const float4*)(g_acc + (size_t)n * 64);
    }

    float acc[8][8];
#pragma unroll
    for (int i = 0; i < 8; i++)
#pragma unroll
        for (int j = 0; j < 8; j++) acc[i][j] = 0.f;

#pragma unroll 1
    for (int k4 = 0; k4 < 16; k4++) {
        float4 xv[8];
#pragma unroll
        for (int i = 0; i < 8; i++) xv[i] = __ldg(&xr[i][k4]);
#pragma unroll
        for (int kk = 0; kk < 4; kk++) {
            const float* wrow = &Ws[(k4 * 4 + kk) * 128 + c0];
            float4 w0 = *(const float4*)&wrow[0];
            float4 w1 = *(const float4*)&wrow[4];
#pragma unroll
            for (int i = 0; i < 8; i++) {
                float xs = elem4(xv[i], kk);
                acc[i][0] += xs * w0.x; acc[i][1] += xs * w0.y;
                acc[i][2] += xs * w0.z; acc[i][3] += xs * w0.w;
                acc[i][4] += xs * w1.x; acc[i][5] += xs * w1.y;
                acc[i][6] += xs * w1.z; acc[i][7] += xs * w1.w;
            }
        }
    }
    // store h2
#pragma unroll
    for (int i = 0; i < 8; i++) {
        int n = n0 + i;
        if (n >= N_NODES) break;
        float* hout = &g_h2[(size_t)n * 128 + c0];
        *(float4*)&hout[0] = make_float4(acc[i][0], acc[i][1], acc[i][2], acc[i][3]);
        *(float4*)&hout[4] = make_float4(acc[i][4], acc[i][5], acc[i][6], acc[i][7]);
    }
    // attention scores: att_src/att_dst are [2,64] flattened = 128 -> index c0+j
    float4 sa0 = __ldg((const float4*)&as_[c0]);
    float4 sa1 = __ldg((const float4*)&as_[c0 + 4]);
    float4 da0 = __ldg((const float4*)&ad_[c0]);
    float4 da1 = __ldg((const float4*)&ad_[c0 + 4]);
    int head = cg >> 3;
#pragma unroll
    for (int i = 0; i < 8; i++) {
        float ps = acc[i][0] * sa0.x + acc[i][1] * sa0.y + acc[i][2] * sa0.z + acc[i][3] * sa0.w
                 + acc[i][4] * sa1.x + acc[i][5] * sa1.y + acc[i][6] * sa1.z + acc[i][7] * sa1.w;
        float pd = acc[i][0] * da0.x + acc[i][1] * da0.y + acc[i][2] * da0.z + acc[i][3] * da0.w
                 + acc[i][4] * da1.x + acc[i][5] * da1.y + acc[i][6] * da1.z + acc[i][7] * da1.w;
#pragma unroll
        for (int off = 1; off < 8; off <<= 1) {
            ps += __shfl_xor_sync(0xffffffffu, ps, off);
            pd += __shfl_xor_sync(0xffffffffu, pd, off);
        }
        int n = n0 + i;
        if ((cg & 7) == 0 && n < N_NODES) {
            g_ss[2 * n + head] = ps;
            g_sd[2 * n + head] = pd;
            g_denom[2 * n + head] = expf(leaky(ps + pd));   // self-loop term
        }
    }
}

// ---------------- softmax denominator over edges ------------------------------
__global__ void k_denom_edges(const int* __restrict__ src, const int* __restrict__ dst) {
    int g = blockIdx.x * blockDim.x + threadIdx.x;
    if (g >= 2 * E_EDGES) return;
    int e = g >> 1, h = g & 1;
    int s = __ldg(&src[e]);
    int d = __ldg(&dst[e]);
    float a = leaky(g_ss[2 * s + h] + g_sd[2 * d + h]);
    atomicAdd(&g_denom[2 * d + h], expf(a));
}

// ---------------- GAT aggregation (head-mean folded: 64-wide accumulator) ----
__global__ void k_gat_self() {
    int t = blockIdx.x * blockDim.x + threadIdx.x;
    if (t >= N_NODES * 16) return;
    int n = t >> 4, q = t & 15;
    float ex0 = expf(leaky(g_ss[2 * n] + g_sd[2 * n]));
    float ex1 = expf(leaky(g_ss[2 * n + 1] + g_sd[2 * n + 1]));
    float c0 = ex0 / fmaxf(g_denom[2 * n], 1e-16f);
    float c1 = ex1 / fmaxf(g_denom[2 * n + 1], 1e-16f);
    const float* hr = &g_h2[(size_t)n * 128];
    float4 f0 = *(const float4*)&hr[q * 4];
    float4 f1 = *(const float4*)&hr[64 + q * 4];
    *(float4*)&g_out_acc[(size_t)n * 64 + q * 4] =
        make_float4(0.5f * (c0 * f0.x + c1 * f1.x),
                    0.5f * (c0 * f0.y + c1 * f1.y),
                    0.5f * (c0 * f0.z + c1 * f1.z),
                    0.5f * (c0 * f0.w + c1 * f1.w));
}

__global__ void k_gat_edges(const int* __restrict__ src, const int* __restrict__ dst) {
    int g = blockIdx.x * blockDim.x + threadIdx.x;
    int e = g >> 4;
    if (e >= E_EDGES) return;
    int t = threadIdx.x & 15;
    int s = __ldg(&src[e]);
    int d = __ldg(&dst[e]);
    float coef = 0.f;
    if (t < 2) {
        float a = leaky(g_ss[2 * s + t] + g_sd[2 * d + t]);
        coef = expf(a) / fmaxf(g_denom[2 * d + t], 1e-16f);
    }
    float c0 = __shfl_sync(0xffffffffu, coef, 0, 16);
    float c1 = __shfl_sync(0xffffffffu, coef, 1, 16);
    const float* hr = &g_h2[(size_t)s * 128];
    float4 f0 = *(const float4*)&hr[t * 4];
    float4 f1 = *(const float4*)&hr[64 + t * 4];
    red_add_v4(&g_out_acc[(size_t)d * 64 + t * 4],
               make_float4(0.5f * (c0 * f0.x + c1 * f1.x),
                           0.5f * (c0 * f0.y + c1 * f1.y),
                           0.5f * (c0 * f0.z + c1 * f1.z),
                           0.5f * (c0 * f0.w + c1 * f1.w)));
}

__global__ void k_final(const float* __restrict__ b, float* __restrict__ out) {
    int t = blockIdx.x * blockDim.x + threadIdx.x;
    if (t >= N_NODES * 16) return;
    int q = t & 15;
    float4 a = *(const float4*)&g_out_acc[(size_t)t * 4];
    float4 bv = *(const float4*)&b[q * 4];
    *(float4*)&out[(size_t)t * 4] =
        make_float4(fmaxf(a.x + bv.x, 0.f), fmaxf(a.y + bv.y, 0.f),
                    fmaxf(a.z + bv.z, 0.f), fmaxf(a.w + bv.w, 0.f));
}

// ---------------- launch -----------------------------------------------------
extern "C" void kernel_launch(void* const* d_in, const int* in_sizes, int n_in,
                              void* d_out, int out_size) {
    const float* x       = (const float*)d_in[0];
    const int*   ei      = (const int*)d_in[1];
    const float* ew      = (const float*)d_in[2];
    const float* gcn_w   = (const float*)d_in[3];
    const float* gcn_b   = (const float*)d_in[4];
    const float* gat_w   = (const float*)d_in[5];
    const float* att_src = (const float*)d_in[6];
    const float* att_dst = (const float*)d_in[7];
    const float* gat_b   = (const float*)d_in[8];
    float* out = (float*)d_out;
    const int* src = ei;
    const int* dst = ei + E_EDGES;

    const int B = 256;
    // degrees / normalization (needed by gemm1 epilogue)
    k_deg_init<<<(N_NODES + B - 1) / B, B>>>();
    k_deg_edges<<<(E_EDGES + B - 1) / B, B>>>(dst, ew);
    k_dinv<<<(N_NODES + B - 1) / B, B>>>();
    // GCN
    k_gemm1<<<(N_NODES + 255) / 256, B>>>(x, gcn_w);
    k_gcn_edges<<<(E_EDGES * 16 + B - 1) / B, B>>>(src, dst, ew);
    k_gcn_final<<<(N_NODES * 16 + B - 1) / B, B>>>(gcn_b);
    // GAT
    k_gemm2<<<(N_NODES + 127) / 128, B>>>(gat_w, att_src, att_dst);
    k_denom_edges<<<(2 * E_EDGES + B - 1) / B, B>>>(src, dst);
    k_gat_self<<<(N_NODES * 16 + B - 1) / B, B>>>();
    k_gat_edges<<<(E_EDGES * 16 + B - 1) / B, B>>>(src, dst);
    k_final<<<(N_NODES * 16 + B - 1) / B, B>>>(gat_b, out);
}

// round 5
// speedup vs baseline: 1.3780x; 1.3780x over previous
#include <cuda_runtime.h>
#include <math.h>

#define N_NODES 100000
#define E_EDGES 1600000
// HID = 64, IN = 128, HEADS = 2

// ---------------- scratch (device globals; no allocations allowed) ----------
__device__ float g_dinv[N_NODES];              // deg -> dinv (in place)
__device__ float g_h[N_NODES * 64];            // x @ gcn_w
__device__ float g_acc[N_NODES * 64];          // GCN accumulator -> hg after relu (in place)
__device__ float g_h2[N_NODES * 128];          // hg @ gat_w  [N, 2 heads, 64]
__device__ float g_ss[N_NODES * 2];            // score_src per (node, head)
__device__ float g_sd[N_NODES * 2];            // score_dst per (node, head)
__device__ float g_denom[N_NODES * 2];         // softmax denominator (no max shift)
__device__ float g_out_acc[N_NODES * 64];      // GAT accumulator (head-mean folded)

// ---------------- helpers ----------------------------------------------------
__device__ __forceinline__ void red_add_v4(float* addr, float4 v) {
    asm volatile("red.global.add.v4.f32 [%0], {%1, %2, %3, %4};"
                 :: "l"(addr), "f"(v.x), "f"(v.y), "f"(v.z), "f"(v.w)
                 : "memory");
}
__device__ __forceinline__ float leaky(float a) {
    return a >= 0.f ? a : 0.2f * a;
}
__device__ __forceinline__ float elem4(float4 v, int kk) {
    return (kk == 0) ? v.x : (kk == 1) ? v.y : (kk == 2) ? v.z : v.w;
}

// ---------------- degree / norm ----------------------------------------------
__global__ void k_deg_init() {
    int t = blockIdx.x * blockDim.x + threadIdx.x;
    if (t < N_NODES) g_dinv[t] = 1.0f;   // self-loop weight 1
}
__global__ void k_deg_edges(const int* __restrict__ dst, const float* __restrict__ ew) {
    int e = blockIdx.x * blockDim.x + threadIdx.x;
    if (e < E_EDGES) atomicAdd(&g_dinv[dst[e]], ew[e]);
}
__global__ void k_dinv() {
    int t = blockIdx.x * blockDim.x + threadIdx.x;
    if (t < N_NODES) g_dinv[t] = rsqrtf(g_dinv[t]);   // deg >= 1 always
}

// ---------------- GEMM1: g_h = x[N,128] @ gcn_w[128,64]  (+ gcn self fold) ---
// 4 nodes x 8 cols per thread (regs ~80, 3 CTAs/SM — the latency-hiding
// sweet spot found in R3; R4's 8-node blocking tanked occupancy).
// Epilogue also writes g_acc = dinv^2 * h  (GCN self-loop term).
__global__ void k_gemm1(const float* __restrict__ x, const float* __restrict__ W) {
    __shared__ float Ws[128 * 64];
    int tid = threadIdx.x;
    for (int i = tid * 4; i < 128 * 64; i += 256 * 4)
        *(float4*)&Ws[i] = *(const float4*)&W[i];
    __syncthreads();

    int cg = tid & 7;          // cols cg*8 .. cg*8+7
    int ng = tid >> 3;         // node group (0..31)
    int n0 = blockIdx.x * 128 + ng * 4;
    int c0 = cg * 8;

    const float4* xr[4];
#pragma unroll
    for (int i = 0; i < 4; i++) {
        int n = n0 + i; if (n >= N_NODES) n = N_NODES - 1;
        xr[i] = (const float4*)(x + (size_t)n * 128);
    }

    float acc[4][8];
#pragma unroll
    for (int i = 0; i < 4; i++)
#pragma unroll
        for (int j = 0; j < 8; j++) acc[i][j] = 0.f;

#pragma unroll 1
    for (int k4 = 0; k4 < 32; k4++) {
        float4 xv[4];
#pragma unroll
        for (int i = 0; i < 4; i++) xv[i] = __ldg(&xr[i][k4]);
#pragma unroll
        for (int kk = 0; kk < 4; kk++) {
            const float* wrow = &Ws[(k4 * 4 + kk) * 64 + c0];
            float4 w0 = *(const float4*)&wrow[0];
            float4 w1 = *(const float4*)&wrow[4];
#pragma unroll
            for (int i = 0; i < 4; i++) {
                float xs = elem4(xv[i], kk);
                acc[i][0] += xs * w0.x; acc[i][1] += xs * w0.y;
                acc[i][2] += xs * w0.z; acc[i][3] += xs * w0.w;
                acc[i][4] += xs * w1.x; acc[i][5] += xs * w1.y;
                acc[i][6] += xs * w1.z; acc[i][7] += xs * w1.w;
            }
        }
    }
#pragma unroll
    for (int i = 0; i < 4; i++) {
        int n = n0 + i;
        if (n >= N_NODES) break;
        float di = g_dinv[n];
        float c = di * di;
        float* hout = &g_h[(size_t)n * 64 + c0];
        float* aout = &g_acc[(size_t)n * 64 + c0];
        *(float4*)&hout[0] = make_float4(acc[i][0], acc[i][1], acc[i][2], acc[i][3]);
        *(float4*)&hout[4] = make_float4(acc[i][4], acc[i][5], acc[i][6], acc[i][7]);
        *(float4*)&aout[0] = make_float4(c * acc[i][0], c * acc[i][1], c * acc[i][2], c * acc[i][3]);
        *(float4*)&aout[4] = make_float4(c * acc[i][4], c * acc[i][5], c * acc[i][6], c * acc[i][7]);
    }
}

// ---------------- GCN edge aggregation ---------------------------------------
__global__ void k_gcn_edges(const int* __restrict__ src, const int* __restrict__ dst,
                            const float* __restrict__ ew) {
    int g = blockIdx.x * blockDim.x + threadIdx.x;
    int e = g >> 4;
    if (e >= E_EDGES) return;
    int t = threadIdx.x & 15;
    int s = __ldg(&src[e]);
    int d = __ldg(&dst[e]);
    float norm = 0.f;
    if (t == 0) norm = g_dinv[s] * __ldg(&ew[e]) * g_dinv[d];
    norm = __shfl_sync(0xffffffffu, norm, 0, 16);
    float4 h = *(const float4*)&g_h[(size_t)s * 64 + t * 4];
    red_add_v4(&g_acc[(size_t)d * 64 + t * 4],
               make_float4(norm * h.x, norm * h.y, norm * h.z, norm * h.w));
}

__global__ void k_gcn_final(const float* __restrict__ b) {
    int t = blockIdx.x * blockDim.x + threadIdx.x;
    if (t >= N_NODES * 16) return;
    int q = t & 15;
    float4 a = *(const float4*)&g_acc[(size_t)t * 4];
    float4 bv = *(const float4*)&b[q * 4];
    a.x = fmaxf(a.x + bv.x, 0.f);
    a.y = fmaxf(a.y + bv.y, 0.f);
    a.z = fmaxf(a.z + bv.z, 0.f);
    a.w = fmaxf(a.w + bv.w, 0.f);
    *(float4*)&g_acc[(size_t)t * 4] = a;    // g_acc is now hg
}

// ---------------- GEMM2: g_h2 = hg[N,64] @ gat_w[64,128] ---------------------
// 4 nodes x 8 cols per thread; 16 col-groups x 16 node-groups -> 64 nodes/blk.
// Epilogue: per-node attention scores (shfl-reduced over the 8-lane col group)
// + softmax denominator init with the self-loop term (no max shift).
__global__ void k_gemm2(const float* __restrict__ W, const float* __restrict__ as_,
                        const float* __restrict__ ad_) {
    __shared__ float Ws[64 * 128];
    int tid = threadIdx.x;
    for (int i = tid * 4; i < 64 * 128; i += 256 * 4)
        *(float4*)&Ws[i] = *(const float4*)&W[i];
    __syncthreads();

    int cg = tid & 15;         // cols cg*8 .. cg*8+7  (cg<8: head0, cg>=8: head1)
    int ng = tid >> 4;         // node group (0..15)
    int n0 = blockIdx.x * 64 + ng * 4;
    int c0 = cg * 8;

    const float4* xr[4];
#pragma unroll
    for (int i = 0; i < 4; i++) {
        int n = n0 + i; if (n >= N_NODES) n = N_NODES - 1;
        xr[i] = (const float4*)(g_acc + (size_t)n * 64);
    }

    float acc[4][8];
#pragma unroll
    for (int i = 0; i < 4; i++)
#pragma unroll
        for (int j = 0; j < 8; j++) acc[i][j] = 0.f;

#pragma unroll 1
    for (int k4 = 0; k4 < 16; k4++) {
        float4 xv[4];
#pragma unroll
        for (int i = 0; i < 4; i++) xv[i] = __ldg(&xr[i][k4]);
#pragma unroll
        for (int kk = 0; kk < 4; kk++) {
            const float* wrow = &Ws[(k4 * 4 + kk) * 128 + c0];
            float4 w0 = *(const float4*)&wrow[0];
            float4 w1 = *(const float4*)&wrow[4];
#pragma unroll
            for (int i = 0; i < 4; i++) {
                float xs = elem4(xv[i], kk);
                acc[i][0] += xs * w0.x; acc[i][1] += xs * w0.y;
                acc[i][2] += xs * w0.z; acc[i][3] += xs * w0.w;
                acc[i][4] += xs * w1.x; acc[i][5] += xs * w1.y;
                acc[i][6] += xs * w1.z; acc[i][7] += xs * w1.w;
            }
        }
    }
    // store h2
#pragma unroll
    for (int i = 0; i < 4; i++) {
        int n = n0 + i;
        if (n >= N_NODES) break;
        float* hout = &g_h2[(size_t)n * 128 + c0];
        *(float4*)&hout[0] = make_float4(acc[i][0], acc[i][1], acc[i][2], acc[i][3]);
        *(float4*)&hout[4] = make_float4(acc[i][4], acc[i][5], acc[i][6], acc[i][7]);
    }
    // attention scores: att_src/att_dst are [2,64] flattened = 128 -> index c0+j
    float4 sa0 = __ldg((const float4*)&as_[c0]);
    float4 sa1 = __ldg((const float4*)&as_[c0 + 4]);
    float4 da0 = __ldg((const float4*)&ad_[c0]);
    float4 da1 = __ldg((const float4*)&ad_[c0 + 4]);
    int head = cg >> 3;
#pragma unroll
    for (int i = 0; i < 4; i++) {
        float ps = acc[i][0] * sa0.x + acc[i][1] * sa0.y + acc[i][2] * sa0.z + acc[i][3] * sa0.w
                 + acc[i][4] * sa1.x + acc[i][5] * sa1.y + acc[i][6] * sa1.z + acc[i][7] * sa1.w;
        float pd = acc[i][0] * da0.x + acc[i][1] * da0.y + acc[i][2] * da0.z + acc[i][3] * da0.w
                 + acc[i][4] * da1.x + acc[i][5] * da1.y + acc[i][6] * da1.z + acc[i][7] * da1.w;
#pragma unroll
        for (int off = 1; off < 8; off <<= 1) {
            ps += __shfl_xor_sync(0xffffffffu, ps, off);
            pd += __shfl_xor_sync(0xffffffffu, pd, off);
        }
        int n = n0 + i;
        if ((cg & 7) == 0 && n < N_NODES) {
            g_ss[2 * n + head] = ps;
            g_sd[2 * n + head] = pd;
            g_denom[2 * n + head] = expf(leaky(ps + pd));   // self-loop term
        }
    }
}

// ---------------- softmax denominator over edges ------------------------------
__global__ void k_denom_edges(const int* __restrict__ src, const int* __restrict__ dst) {
    int g = blockIdx.x * blockDim.x + threadIdx.x;
    if (g >= 2 * E_EDGES) return;
    int e = g >> 1, h = g & 1;
    int s = __ldg(&src[e]);
    int d = __ldg(&dst[e]);
    float a = leaky(g_ss[2 * s + h] + g_sd[2 * d + h]);
    atomicAdd(&g_denom[2 * d + h], expf(a));
}

// ---------------- GAT aggregation (head-mean folded: 64-wide accumulator) ----
__global__ void k_gat_self() {
    int t = blockIdx.x * blockDim.x + threadIdx.x;
    if (t >= N_NODES * 16) return;
    int n = t >> 4, q = t & 15;
    float ex0 = expf(leaky(g_ss[2 * n] + g_sd[2 * n]));
    float ex1 = expf(leaky(g_ss[2 * n + 1] + g_sd[2 * n + 1]));
    float c0 = ex0 / fmaxf(g_denom[2 * n], 1e-16f);
    float c1 = ex1 / fmaxf(g_denom[2 * n + 1], 1e-16f);
    const float* hr = &g_h2[(size_t)n * 128];
    float4 f0 = *(const float4*)&hr[q * 4];
    float4 f1 = *(const float4*)&hr[64 + q * 4];
    *(float4*)&g_out_acc[(size_t)n * 64 + q * 4] =
        make_float4(0.5f * (c0 * f0.x + c1 * f1.x),
                    0.5f * (c0 * f0.y + c1 * f1.y),
                    0.5f * (c0 * f0.z + c1 * f1.z),
                    0.5f * (c0 * f0.w + c1 * f1.w));
}

__global__ void k_gat_edges(const int* __restrict__ src, const int* __restrict__ dst) {
    int g = blockIdx.x * blockDim.x + threadIdx.x;
    int e = g >> 4;
    if (e >= E_EDGES) return;
    int t = threadIdx.x & 15;
    int s = __ldg(&src[e]);
    int d = __ldg(&dst[e]);
    float coef = 0.f;
    if (t < 2) {
        float a = leaky(g_ss[2 * s + t] + g_sd[2 * d + t]);
        coef = expf(a) / fmaxf(g_denom[2 * d + t], 1e-16f);
    }
    float c0 = __shfl_sync(0xffffffffu, coef, 0, 16);
    float c1 = __shfl_sync(0xffffffffu, coef, 1, 16);
    const float* hr = &g_h2[(size_t)s * 128];
    float4 f0 = *(const float4*)&hr[t * 4];
    float4 f1 = *(const float4*)&hr[64 + t * 4];
    red_add_v4(&g_out_acc[(size_t)d * 64 + t * 4],
               make_float4(0.5f * (c0 * f0.x + c1 * f1.x),
                           0.5f * (c0 * f0.y + c1 * f1.y),
                           0.5f * (c0 * f0.z + c1 * f1.z),
                           0.5f * (c0 * f0.w + c1 * f1.w)));
}

__global__ void k_final(const float* __restrict__ b, float* __restrict__ out) {
    int t = blockIdx.x * blockDim.x + threadIdx.x;
    if (t >= N_NODES * 16) return;
    int q = t & 15;
    float4 a = *(const float4*)&g_out_acc[(size_t)t * 4];
    float4 bv = *(const float4*)&b[q * 4];
    *(float4*)&out[(size_t)t * 4] =
        make_float4(fmaxf(a.x + bv.x, 0.f), fmaxf(a.y + bv.y, 0.f),
                    fmaxf(a.z + bv.z, 0.f), fmaxf(a.w + bv.w, 0.f));
}

// ---------------- launch -----------------------------------------------------
extern "C" void kernel_launch(void* const* d_in, const int* in_sizes, int n_in,
                              void* d_out, int out_size) {
    const float* x       = (const float*)d_in[0];
    const int*   ei      = (const int*)d_in[1];
    const float* ew      = (const float*)d_in[2];
    const float* gcn_w   = (const float*)d_in[3];
    const float* gcn_b   = (const float*)d_in[4];
    const float* gat_w   = (const float*)d_in[5];
    const float* att_src = (const float*)d_in[6];
    const float* att_dst = (const float*)d_in[7];
    const float* gat_b   = (const float*)d_in[8];
    float* out = (float*)d_out;
    const int* src = ei;
    const int* dst = ei + E_EDGES;

    const int B = 256;
    // degrees / normalization (needed by gemm1 epilogue)
    k_deg_init<<<(N_NODES + B - 1) / B, B>>>();
    k_deg_edges<<<(E_EDGES + B - 1) / B, B>>>(dst, ew);
    k_dinv<<<(N_NODES + B - 1) / B, B>>>();
    // GCN
    k_gemm1<<<(N_NODES + 127) / 128, B>>>(x, gcn_w);
    k_gcn_edges<<<(E_EDGES * 16 + B - 1) / B, B>>>(src, dst, ew);
    k_gcn_final<<<(N_NODES * 16 + B - 1) / B, B>>>(gcn_b);
    // GAT
    k_gemm2<<<(N_NODES + 63) / 64, B>>>(gat_w, att_src, att_dst);
    k_denom_edges<<<(2 * E_EDGES + B - 1) / B, B>>>(src, dst);
    k_gat_self<<<(N_NODES * 16 + B - 1) / B, B>>>();
    k_gat_edges<<<(E_EDGES * 16 + B - 1) / B, B>>>(src, dst);
    k_final<<<(N_NODES * 16 + B - 1) / B, B>>>(gat_b, out);
}